// round 10
// baseline (speedup 1.0000x reference)
#include <cuda_runtime.h>
#include <cstdint>

// out[i] = W[inputs[i] - 1];  N = 16384*200 = 3,276,800;  W: 200 floats.
// Index dtype probe: idx_raw[1]==0 -> int64 (high word of elem 0), else int32.
//
// R7 recipe (best: 8.10us) with 1024-thread CTAs: grid 400 x 1024,
// 1 unit/thread (unit = 8 out elems; 400*1024*8 = N exactly).
// 2 CTAs/SM = 2048 threads (full cap), half the CTA prologues of R7.
// v8.b32 ops, L2 evict_last on idx / evict_first on out, replicated-smem
// conflict-free gather, index loads front-batched ahead of the W fill.

#define N_TOTAL   (16384 * 200)
#define MAX_RANKS 200
#define TPB       1024
#define NBLK      (N_TOTAL / (TPB * 8))   // 400

struct V8 { uint32_t r0,r1,r2,r3,r4,r5,r6,r7; };

__device__ __forceinline__ V8 ldg_pin8(const void* p) {
    V8 v;
    asm volatile("ld.global.nc.L2::evict_last.v8.b32 "
                 "{%0,%1,%2,%3,%4,%5,%6,%7}, [%8];"
                 : "=r"(v.r0), "=r"(v.r1), "=r"(v.r2), "=r"(v.r3),
                   "=r"(v.r4), "=r"(v.r5), "=r"(v.r6), "=r"(v.r7)
                 : "l"(p));
    return v;
}

__device__ __forceinline__ void stg_stream8(void* p, const float* f) {
    asm volatile("st.global.L2::evict_first.v8.b32 "
                 "[%0], {%1,%2,%3,%4,%5,%6,%7,%8};"
                 :: "l"(p),
                    "f"(f[0]), "f"(f[1]), "f"(f[2]), "f"(f[3]),
                    "f"(f[4]), "f"(f[5]), "f"(f[6]), "f"(f[7])
                 : "memory");
}

__global__ __launch_bounds__(TPB)
void bias_gather_kernel(const uint32_t* __restrict__ idx_raw,
                        const float* __restrict__ W,
                        float* __restrict__ out)
{
    // 32-way replicated W: sW[rank*32 + lane] -> bank == lane, conflict-free.
    __shared__ float sW[MAX_RANKS * 32];

    const int tid  = threadIdx.x;
    const int lane = tid & 31;
    const int wid  = tid >> 5;

    const long long u = (long long)blockIdx.x * TPB + tid;   // < 409,600

    // ---- Front-batch all global index loads (overlap with W fill) ----
    const uint32_t probe = idx_raw[1];          // 0 => int64 indices
    const bool is64 = (probe == 0u);
    const char* ib = reinterpret_cast<const char*>(idx_raw);

    V8 a, b;
    if (is64) {
        a = ldg_pin8(ib + u * 64);       // 8 int64 idx: low words at even regs
        b = ldg_pin8(ib + u * 64 + 32);
    } else {
        a = ldg_pin8(ib + u * 32);       // 8 int32 idx
    }

    // ---- Fill replicated W while index loads are in flight ----
    #pragma unroll
    for (int k = wid; k < MAX_RANKS; k += TPB / 32) {
        float v = W[k];                  // warp-uniform addr: 1 sector
        sW[k * 32 + lane] = v;           // conflict-free STS
    }
    __syncthreads();

    // ---- Conflict-free gather + one streaming 256-bit store ----
    float r[8];
    if (is64) {
        r[0] = sW[((int)a.r0 - 1) * 32 + lane];
        r[1] = sW[((int)a.r2 - 1) * 32 + lane];
        r[2] = sW[((int)a.r4 - 1) * 32 + lane];
        r[3] = sW[((int)a.r6 - 1) * 32 + lane];
        r[4] = sW[((int)b.r0 - 1) * 32 + lane];
        r[5] = sW[((int)b.r2 - 1) * 32 + lane];
        r[6] = sW[((int)b.r4 - 1) * 32 + lane];
        r[7] = sW[((int)b.r6 - 1) * 32 + lane];
    } else {
        r[0] = sW[((int)a.r0 - 1) * 32 + lane];
        r[1] = sW[((int)a.r1 - 1) * 32 + lane];
        r[2] = sW[((int)a.r2 - 1) * 32 + lane];
        r[3] = sW[((int)a.r3 - 1) * 32 + lane];
        r[4] = sW[((int)a.r4 - 1) * 32 + lane];
        r[5] = sW[((int)a.r5 - 1) * 32 + lane];
        r[6] = sW[((int)a.r6 - 1) * 32 + lane];
        r[7] = sW[((int)a.r7 - 1) * 32 + lane];
    }

    stg_stream8(reinterpret_cast<char*>(out) + u * 32, r);
}

extern "C" void kernel_launch(void* const* d_in, const int* in_sizes, int n_in,
                              void* d_out, int out_size)
{
    const uint32_t* idx = (const uint32_t*)d_in[0];  // inputs [16384, 200]
    const float*    W   = (const float*)d_in[1];     // [200, 1]
    float*          out = (float*)d_out;

    bias_gather_kernel<<<NBLK, TPB>>>(idx, W, out);
}